// round 7
// baseline (speedup 1.0000x reference)
#include <cuda_runtime.h>
#include <cstdint>

// ---------------- problem constants ----------------
#define BB      8
#define HEADS   4
#define NQ      3136
#define NKV     784
#define DH      32
#define CC      128
#define TN      64                 // kv tile (12 full tiles + tail of 16)
#define NFULL   12
#define VSTRIDE 26624              // 13 tiles * 2048 floats per (b,h)
#define QPB     ((BB * NQ) / 64)   // q-proj blocks = 392

typedef unsigned long long u64;

// ---------------- scratch (device globals; no allocation) ----------------
__device__ float g_q [BB * HEADS * NQ  * DH];      // permuted d', tf32, scaled by 2^-2.5*log2e
__device__ float g_k [BB * HEADS * NKV * DH];      // permuted d' + kv-slot permuted, tf32
__device__ float g_v [BB * HEADS * VSTRIDE];       // tile-permuted Vp, tf32
__device__ float g_xr[BB * NKV * CC];
__device__ float g_ao[BB * NQ  * CC];

// ---------------- helpers ----------------
__device__ __forceinline__ u64 pack2(float x, float y) {
    u64 r; asm("mov.b64 %0, {%1, %2};" : "=l"(r) : "f"(x), "f"(y)); return r;
}
__device__ __forceinline__ void unpack2(u64 v, float& x, float& y) {
    asm("mov.b64 {%0, %1}, %2;" : "=f"(x), "=f"(y) : "l"(v));
}
__device__ __forceinline__ u64 fma2(u64 a, u64 b, u64 c) {
    u64 d; asm("fma.rn.f32x2 %0, %1, %2, %3;" : "=l"(d) : "l"(a), "l"(b), "l"(c)); return d;
}
__device__ __forceinline__ float to_tf32(float x) {
    float r; asm("cvt.rna.tf32.f32 %0, %1;" : "=f"(r) : "f"(x)); return r;
}
__device__ __forceinline__ float ex2(float x) {
    float r; asm("ex2.approx.f32 %0, %1;" : "=f"(r) : "f"(x)); return r;
}
__device__ __forceinline__ unsigned smem_u32(const void* p) {
    return (unsigned)__cvta_generic_to_shared(p);
}
__device__ __forceinline__ void cp16(unsigned dst, const void* src) {
    asm volatile("cp.async.cg.shared.global [%0], [%1], 16;\n" :: "r"(dst), "l"(src));
}
__device__ __forceinline__ void cp_commit() {
    asm volatile("cp.async.commit_group;\n" ::: "memory");
}
__device__ __forceinline__ void cp_wait0() {
    asm volatile("cp.async.wait_group 0;\n" ::: "memory");
}

// mma.sync m16n8k8 tf32 (base PTX, sm_80+)
__device__ __forceinline__ void mma8(float c[4], float a0, float a1, float a2, float a3,
                                     float b0, float b1) {
    asm volatile(
        "mma.sync.aligned.m16n8k8.row.col.f32.tf32.tf32.f32 "
        "{%0,%1,%2,%3}, {%4,%5,%6,%7}, {%8,%9}, {%0,%1,%2,%3};"
        : "+f"(c[0]), "+f"(c[1]), "+f"(c[2]), "+f"(c[3])
        : "r"(__float_as_uint(a0)), "r"(__float_as_uint(a1)),
          "r"(__float_as_uint(a2)), "r"(__float_as_uint(a3)),
          "r"(__float_as_uint(b0)), "r"(__float_as_uint(b1)));
}

// ---------------- projection GEMM: Y = X(Mx128) @ W(128x128) + b ------
// mode 0: plain.  mode 1: K (head-split, d-permute, kv-slot permute, tf32)
// mode 2: Q (head-split, d-permute, tf32, scaled by 2^-2.5 * log2e)
// mode 4: V (head-split, kv-tile permute Vp[r%4][d][r/4], tf32)
__device__ __forceinline__ void proj_body(
    const float* __restrict__ X, const float* __restrict__ W,
    const float* __restrict__ bias, float* __restrict__ Y,
    int rowb, int M, int RPB, int mode)
{
    __shared__ __align__(16) float Xs[32][66];
    __shared__ __align__(16) float Ws[32][128];

    const int tid   = threadIdx.x;
    const int col_t = tid & 31;
    const int row_t = tid >> 5;

    u64 acc2[4][4];
#pragma unroll
    for (int rp = 0; rp < 4; rp++)
#pragma unroll
        for (int c = 0; c < 4; c++) acc2[rp][c] = 0ULL;

    for (int kc = 0; kc < 128; kc += 32) {
        __syncthreads();
#pragma unroll
        for (int i = 0; i < 8; i++) {
            int idx = tid + i * 256;
            int r = idx >> 5, kk = idx & 31;
            Xs[kk][r] = X[(size_t)(rowb + r) * CC + kc + kk];
        }
#pragma unroll
        for (int i = 0; i < 16; i++) {
            int idx = tid + i * 256;
            int kk = idx >> 7, cc2 = idx & 127;
            Ws[kk][cc2] = W[(size_t)(kc + kk) * CC + cc2];
        }
        __syncthreads();
#pragma unroll
        for (int kk = 0; kk < 32; kk++) {
            float4 wv = *(const float4*)&Ws[kk][col_t * 4];
            u64 wd0 = pack2(wv.x, wv.x);
            u64 wd1 = pack2(wv.y, wv.y);
            u64 wd2 = pack2(wv.z, wv.z);
            u64 wd3 = pack2(wv.w, wv.w);
            const u64* xrow = (const u64*)&Xs[kk][row_t * 8];
#pragma unroll
            for (int rp = 0; rp < 4; rp++) {
                u64 xp = xrow[rp];
                acc2[rp][0] = fma2(xp, wd0, acc2[rp][0]);
                acc2[rp][1] = fma2(xp, wd1, acc2[rp][1]);
                acc2[rp][2] = fma2(xp, wd2, acc2[rp][2]);
                acc2[rp][3] = fma2(xp, wd3, acc2[rp][3]);
            }
        }
    }

    const float qscale = 0.25503486f;   // 32^-0.5 * log2(e)
    const int col0 = col_t * 4;
    float4 bv = *(const float4*)&bias[col0];
#pragma unroll
    for (int rp = 0; rp < 4; rp++) {
        float lo[4], hi[4];
#pragma unroll
        for (int c = 0; c < 4; c++) unpack2(acc2[rp][c], lo[c], hi[c]);
        int row0 = rowb + row_t * 8 + 2 * rp;
#pragma unroll
        for (int half = 0; half < 2; half++) {
            int row = row0 + half;
            if (row >= M) continue;
            float* s = half ? hi : lo;
            float o[4];
            o[0] = s[0] + bv.x; o[1] = s[1] + bv.y;
            o[2] = s[2] + bv.z; o[3] = s[3] + bv.w;
            if (mode == 0) {
                *(float4*)&Y[(size_t)row * CC + col0] = make_float4(o[0], o[1], o[2], o[3]);
            } else {
                int b = row / RPB, n = row % RPB;
                int h = col0 >> 5, dbase = col0 & 31;
                if (mode == 4) {
                    int tile = n >> 6, rr = n & 63;
                    float* bp = &Y[(size_t)(b * HEADS + h) * VSTRIDE
                                   + tile * 2048 + (rr & 3) * 512 + (rr >> 2)];
#pragma unroll
                    for (int i = 0; i < 4; i++)
                        bp[(dbase + i) * 16] = to_tf32(o[i]);
                } else {
                    int n2 = n;
                    if (mode == 1)   // kv-slot permute within 8-groups
                        n2 = (n & ~7) | (((n & 3) << 1) | ((n & 7) >> 2));
                    float* bp = &Y[((size_t)(b * HEADS + h) * RPB + n2) * DH];
#pragma unroll
                    for (int i = 0; i < 4; i++) {
                        int d = dbase + i;
                        int dp = (d & 3) * 8 + (d >> 2);
                        float val = (mode == 2) ? o[i] * qscale : o[i];
                        bp[dp] = to_tf32(val);
                    }
                }
            }
        }
    }
}

__global__ __launch_bounds__(256) void proj_kernel(
    const float* __restrict__ X, const float* __restrict__ W,
    const float* __restrict__ bias, float* __restrict__ Y,
    int M, int RPB, int mode)
{
    proj_body(X, W, bias, Y, blockIdx.x * 64, M, RPB, mode);
}

// fused: q projection + spatial-reduction conv (both depend only on x)
__global__ __launch_bounds__(256) void qproj_conv_kernel(
    const float* __restrict__ x,
    const float* __restrict__ Wq, const float* __restrict__ bq, float* __restrict__ Q,
    const float* __restrict__ cw, const float* __restrict__ cb,
    const float* __restrict__ gamma, const float* __restrict__ beta,
    const float* __restrict__ mean, const float* __restrict__ var,
    float* __restrict__ xr)
{
    if (blockIdx.x < QPB) {
        proj_body(x, Wq, bq, Q, blockIdx.x * 64, BB * NQ, NQ, 2);
        return;
    }
    int t = (blockIdx.x - QPB) * 256 + threadIdx.x;
    if (t >= BB * NKV * CC) return;
    int c = t & (CC - 1);
    int p = (t >> 7) % NKV;
    int b = t / (NKV * CC);
    int oy = p / 28, ox = p % 28;

    const float* xb = x + (size_t)b * NQ * CC;
    float s = 0.f;
#pragma unroll
    for (int i = 0; i < 2; i++)
#pragma unroll
        for (int j = 0; j < 2; j++)
            s += xb[(size_t)((2 * oy + i) * 56 + (2 * ox + j)) * CC + c] * cw[c * 4 + i * 2 + j];
    s += cb[c];
    float iv = gamma[c] * rsqrtf(var[c] + 1e-5f);
    xr[t] = s * iv + (beta[c] - mean[c] * iv);
}

__global__ __launch_bounds__(256) void proj_kv_kernel(
    const float* __restrict__ X,
    const float* __restrict__ Wk, const float* __restrict__ bk, float* __restrict__ K,
    const float* __restrict__ Wv, const float* __restrict__ bv, float* __restrict__ V,
    int M, int RPB)
{
    int nb = gridDim.x >> 1;
    int half = blockIdx.x >= nb;
    int rowb = (blockIdx.x - (half ? nb : 0)) * 64;
    if (half) proj_body(X, Wv, bv, V, rowb, M, RPB, 4);
    else      proj_body(X, Wk, bk, K, rowb, M, RPB, 1);
}

// ---------------- mma attention (register-resident P) ----------------
// smem: K 2 x (64 x 36) = 4608 floats; V 2 x (4 x 516) = 4128 floats
#define VS_F    4608
#define SMEM_F  8736

// per-tile body. NF = kv/8 (8 for full 64-kv tiles, 2 for 16-kv tail)
template<int NF>
__device__ __forceinline__ void tile_body(
    const float* __restrict__ Ksm, const float* __restrict__ Vsm,
    const float (&qreg)[4][8], float (&o)[2][4][4], float (&sums)[4],
    const float* const (&rpr)[4], int ktile, int g, int t)
{
    const float L2E = 1.4426950408889634f;
#pragma unroll
    for (int c8 = 0; c8 < NF; c8++) {
        // ---- S chunk = Q @ K^T (K slots pre-permuted: c regs land in PV A-layout)
        const float* kp = Ksm + (8 * c8 + g) * 36 + t * 8;
        float4 k0 = *(const float4*)kp;
        float4 k1 = *(const float4*)(kp + 4);
        float kb[8] = {k0.x, k0.y, k0.z, k0.w, k1.x, k1.y, k1.z, k1.w};
        float c0[4] = {0.f, 0.f, 0.f, 0.f};
        float c1[4] = {0.f, 0.f, 0.f, 0.f};
#pragma unroll
        for (int s = 0; s < 4; s++) {
            mma8(c0, qreg[0][2*s], qreg[1][2*s], qreg[0][2*s+1], qreg[1][2*s+1],
                 kb[2*s], kb[2*s+1]);
            mma8(c1, qreg[2][2*s], qreg[3][2*s], qreg[2][2*s+1], qreg[3][2*s+1],
                 kb[2*s], kb[2*s+1]);
        }
        // ---- bias (cols t, t+4 per row), exp2, sums ----
        int off = ktile + 8 * c8;
        float b00 = rpr[0][off + t], b01 = rpr[0][off + t + 4];
        float b10 = rpr[1][off + t], b11 = rpr[1][off + t + 4];
        float b20 = rpr[2][off + t], b21 = rpr[2][off + t + 4];
        float b30 = rpr[3][off + t], b31 = rpr[3][off + t + 4];
        float p00 = to_tf32(ex2(fmaf(b00, L2E, c0[0])));   // row0, kv t
        float p02 = to_tf32(ex2(fmaf(b01, L2E, c0[1])));   // row0, kv t+4
        float p10 = to_tf32(ex2(fmaf(b10, L2E, c0[2])));   // row1, kv t
        float p12 = to_tf32(ex2(fmaf(b11, L2E, c0[3])));
        float p20 = to_tf32(ex2(fmaf(b20, L2E, c1[0])));
        float p22 = to_tf32(ex2(fmaf(b21, L2E, c1[1])));
        float p30 = to_tf32(ex2(fmaf(b30, L2E, c1[2])));
        float p32 = to_tf32(ex2(fmaf(b31, L2E, c1[3])));
        sums[0] += p00 + p02; sums[1] += p10 + p12;
        sums[2] += p20 + p22; sums[3] += p30 + p32;
        // ---- O += P @ V (A frags direct from registers) ----
        const int posw = (c8 & 1) << 1;
        const int rh   = c8 >> 1;
#pragma unroll
        for (int nf = 0; nf < 4; nf++) {
            int d  = 8 * nf + g;
            int cc = ((d << 2) + rh) ^ ((d >> 1) & 3);     // XOR-swizzled 16B chunk
            float2 bv = *(const float2*)(Vsm + t * 516 + 4 * cc + posw);
            mma8(o[0][nf], p00, p10, p02, p12, bv.x, bv.y);
            mma8(o[1][nf], p20, p30, p22, p32, bv.x, bv.y);
        }
    }
}

__global__ __launch_bounds__(128, 4) void attn_mma_kernel(
    const float* __restrict__ q, const float* __restrict__ k, const float* __restrict__ v,
    const float* __restrict__ relpos, float* __restrict__ out)
{
    __shared__ __align__(16) float dsm[SMEM_F];

    const int b   = blockIdx.z;
    const int h   = blockIdx.y;
    const int qt  = blockIdx.x;
    const int tid = threadIdx.x;
    const int lane = tid & 31, w = tid >> 5;
    const int g = lane >> 2, t = lane & 3;
    const int q0 = qt * 128;

    const float* qb = q + (size_t)(b * HEADS + h) * NQ * DH;
    const float* kb = k + (size_t)(b * HEADS + h) * NKV * DH;
    const float* vb = v + (size_t)(b * HEADS + h) * VSTRIDE;

    // ---- Q fragments (persistent) + bias row pointers ----
    float qreg[4][8];
    int qraw[4];
    const float* rpr[4];
#pragma unroll
    for (int rr = 0; rr < 4; rr++) {
        int qg = q0 + 32 * w + g + 8 * rr;
        qraw[rr] = qg;
        if (qg >= NQ) qg = NQ - 1;
        const float* qp = qb + (size_t)qg * DH + t * 8;
        float4 x0 = *(const float4*)qp;
        float4 x1 = *(const float4*)(qp + 4);
        qreg[rr][0] = x0.x; qreg[rr][1] = x0.y; qreg[rr][2] = x0.z; qreg[rr][3] = x0.w;
        qreg[rr][4] = x1.x; qreg[rr][5] = x1.y; qreg[rr][6] = x1.z; qreg[rr][7] = x1.w;
        rpr[rr] = relpos + ((size_t)h * NQ + qg) * NKV;
    }

    float o[2][4][4];
#pragma unroll
    for (int i = 0; i < 2; i++)
#pragma unroll
        for (int j = 0; j < 4; j++)
#pragma unroll
            for (int c = 0; c < 4; c++) o[i][j][c] = 0.f;
    float sums[4] = {0.f, 0.f, 0.f, 0.f};

    const unsigned kd_base = smem_u32(dsm);
    const unsigned vd_base = smem_u32(dsm + VS_F);

    // prefetch tile 0 (512 K-chunks + 512 V-chunks of 16B)
    {
#pragma unroll
        for (int i = 0; i < 8; i++) {
            int idx = tid + i * 128;
            if (idx < 512) {
                int r = idx >> 3, c = idx & 7;
                cp16(kd_base + r * 144 + c * 16, kb + idx * 4);
            } else {
                int j = idx - 512;
                int dst = (j >> 7) * 129 + ((j & 127) ^ ((j >> 3) & 3));
                cp16(vd_base + dst * 16, vb + j * 4);
            }
        }
    }
    cp_commit();

    for (int tt = 0; tt < 13; tt++) {
        const int buf = tt & 1;
        cp_wait0();
        __syncthreads();

        if (tt + 1 < 13) {
            const int nb = buf ^ 1;
            const unsigned kd = kd_base + nb * 9216;
            const unsigned vd = vd_base + nb * 8256;
            const float* kg = kb + (size_t)(tt + 1) * 2048;
            const float* vg = vb + (size_t)(tt + 1) * 2048;
            if (tt + 1 < NFULL) {
#pragma unroll
                for (int i = 0; i < 8; i++) {
                    int idx = tid + i * 128;
                    if (idx < 512) {
                        int r = idx >> 3, c = idx & 7;
                        cp16(kd + r * 144 + c * 16, kg + idx * 4);
                    } else {
                        int j = idx - 512;
                        int dst = (j >> 7) * 129 + ((j & 127) ^ ((j >> 3) & 3));
                        cp16(vd + dst * 16, vg + j * 4);
                    }
                }
            } else {
                // tail: 16 kv rows -> 128 K-chunks + 128 V-chunks
#pragma unroll
                for (int i = 0; i < 2; i++) {
                    int idx = tid + i * 128;
                    if (idx < 128) {
                        int r = idx >> 3, c = idx & 7;
                        cp16(kd + r * 144 + c * 16, kg + idx * 4);
                    } else {
                        int j = idx - 128;
                        int grp = j >> 5, d = j & 31;
                        int dst = grp * 129 + ((d << 2) ^ ((d >> 1) & 3));
                        cp16(vd + dst * 16, vg + grp * 512 + d * 16);
                    }
                }
            }
        }
        cp_commit();

        const float* Ksm = dsm + buf * 2304;
        const float* Vsm = dsm + VS_F + buf * 2064;
        if (tt < NFULL)
            tile_body<8>(Ksm, Vsm, qreg, o, sums, rpr, tt * TN, g, t);
        else
            tile_body<2>(Ksm, Vsm, qreg, o, sums, rpr, tt * TN, g, t);
    }

    // ---- finalize: quad-reduce row sums, normalize, write ----
    float inv[4];
#pragma unroll
    for (int rr = 0; rr < 4; rr++) {
        float s = sums[rr];
        s += __shfl_xor_sync(0xffffffffu, s, 1);
        s += __shfl_xor_sync(0xffffffffu, s, 2);
        inv[rr] = 1.f / s;
    }
#pragma unroll
    for (int mf = 0; mf < 2; mf++) {
#pragma unroll
        for (int rh = 0; rh < 2; rh++) {
            int rr = 2 * mf + rh;
            int qg = qraw[rr];
            if (qg >= NQ) continue;
            float* op = out + ((size_t)(b * NQ + qg)) * CC + h * 32 + 2 * t;
#pragma unroll
            for (int nf = 0; nf < 4; nf++) {
                float2 val = make_float2(o[mf][nf][2 * rh] * inv[rr],
                                         o[mf][nf][2 * rh + 1] * inv[rr]);
                *(float2*)(op + 8 * nf) = val;
            }
        }
    }
}

// ---------------- launch ----------------
extern "C" void kernel_launch(void* const* d_in, const int* in_sizes, int n_in,
                              void* d_out, int out_size)
{
    const float* x      = (const float*)d_in[0];
    const float* relpos = (const float*)d_in[1];
    const float* Wq     = (const float*)d_in[2];
    const float* bq     = (const float*)d_in[3];
    const float* Wk     = (const float*)d_in[4];
    const float* bk     = (const float*)d_in[5];
    const float* Wv     = (const float*)d_in[6];
    const float* bv     = (const float*)d_in[7];
    const float* cw     = (const float*)d_in[8];
    const float* cb     = (const float*)d_in[9];
    const float* gamma  = (const float*)d_in[10];
    const float* beta   = (const float*)d_in[11];
    const float* mean   = (const float*)d_in[12];
    const float* var    = (const float*)d_in[13];
    const float* Wp     = (const float*)d_in[14];
    const float* bp     = (const float*)d_in[15];
    float* out = (float*)d_out;

    float *q, *k, *v, *xr, *ao;
    cudaGetSymbolAddress((void**)&q,  g_q);
    cudaGetSymbolAddress((void**)&k,  g_k);
    cudaGetSymbolAddress((void**)&v,  g_v);
    cudaGetSymbolAddress((void**)&xr, g_xr);
    cudaGetSymbolAddress((void**)&ao, g_ao);

    // 1) fused q projection + spatial-reduction conv
    int conv_blocks = (BB * NKV * CC + 255) / 256;
    qproj_conv_kernel<<<QPB + conv_blocks, 256>>>(x, Wq, bq, q,
                                                  cw, cb, gamma, beta, mean, var, xr);
    // 2) fused k+v projections (K d+slot-permuted tf32; V tile-permuted tf32)
    proj_kv_kernel<<<2 * (BB * NKV) / 64, 256>>>(xr, Wk, bk, k, Wv, bv, v, BB * NKV, NKV);
    // 3) attention: tensor-core tf32 mma, register-resident P
    dim3 ag((NQ + 127) / 128, HEADS, BB);
    attn_mma_kernel<<<ag, 128>>>(q, k, v, relpos, ao);
    // 4) output projection
    proj_kernel<<<(BB * NQ) / 64, 256>>>(ao, Wp, bp, out, BB * NQ, NQ, 0);
}

// round 8
// speedup vs baseline: 1.1178x; 1.1178x over previous
#include <cuda_runtime.h>
#include <cstdint>

// ---------------- problem constants ----------------
#define BB      8
#define HEADS   4
#define NQ      3136
#define NKV     784
#define DH      32
#define CC      128
#define TN      64                 // kv tile (12 full tiles + tail of 16)
#define NFULL   12
#define VSTRIDE 26624              // 13 tiles * 2048 floats per (b,h)
#define QPB2    ((BB * NQ) / 128)  // mma-proj blocks = 196

typedef unsigned long long u64;

// ---------------- scratch (device globals; no allocation) ----------------
__device__ float g_q [BB * HEADS * NQ  * DH];      // permuted d', tf32, scaled by 32^-.5*log2e
__device__ float g_k [BB * HEADS * NKV * DH];      // permuted d' + kv-slot permuted, tf32
__device__ float g_v [BB * HEADS * VSTRIDE];       // tile-permuted Vp, tf32
__device__ float g_xr[BB * NKV * CC];
__device__ float g_ao[BB * NQ  * CC];

// ---------------- helpers ----------------
__device__ __forceinline__ u64 pack2(float x, float y) {
    u64 r; asm("mov.b64 %0, {%1, %2};" : "=l"(r) : "f"(x), "f"(y)); return r;
}
__device__ __forceinline__ void unpack2(u64 v, float& x, float& y) {
    asm("mov.b64 {%0, %1}, %2;" : "=f"(x), "=f"(y) : "l"(v));
}
__device__ __forceinline__ u64 fma2(u64 a, u64 b, u64 c) {
    u64 d; asm("fma.rn.f32x2 %0, %1, %2, %3;" : "=l"(d) : "l"(a), "l"(b), "l"(c)); return d;
}
__device__ __forceinline__ float to_tf32(float x) {
    float r; asm("cvt.rna.tf32.f32 %0, %1;" : "=f"(r) : "f"(x)); return r;
}
__device__ __forceinline__ float ex2(float x) {
    float r; asm("ex2.approx.f32 %0, %1;" : "=f"(r) : "f"(x)); return r;
}
__device__ __forceinline__ unsigned smem_u32(const void* p) {
    return (unsigned)__cvta_generic_to_shared(p);
}
__device__ __forceinline__ void cp16(unsigned dst, const void* src) {
    asm volatile("cp.async.cg.shared.global [%0], [%1], 16;\n" :: "r"(dst), "l"(src));
}
__device__ __forceinline__ void cp_commit() {
    asm volatile("cp.async.commit_group;\n" ::: "memory");
}
__device__ __forceinline__ void cp_wait0() {
    asm volatile("cp.async.wait_group 0;\n" ::: "memory");
}

// mma.sync m16n8k8 tf32 (base PTX, sm_80+)
__device__ __forceinline__ void mma8(float c[4], float a0, float a1, float a2, float a3,
                                     float b0, float b1) {
    asm volatile(
        "mma.sync.aligned.m16n8k8.row.col.f32.tf32.tf32.f32 "
        "{%0,%1,%2,%3}, {%4,%5,%6,%7}, {%8,%9}, {%0,%1,%2,%3};"
        : "+f"(c[0]), "+f"(c[1]), "+f"(c[2]), "+f"(c[3])
        : "r"(__float_as_uint(a0)), "r"(__float_as_uint(a1)),
          "r"(__float_as_uint(a2)), "r"(__float_as_uint(a3)),
          "r"(__float_as_uint(b0)), "r"(__float_as_uint(b1)));
}

// ---------------- tensor-core projection: Y = X(Mx128) @ W(128x128) + b ----
// CTA = 128 rows x 128 cols, 8 warps (4m x 2n), warp tile 32x64, K chunks of 32.
// mode 0: plain fp32 row-major out.  mode 2: Q out (head-split, d-permute,
// tf32, scaled by 32^-0.5 * log2e).
__device__ __forceinline__ void proj_mma_body(
    const float* __restrict__ X, const float* __restrict__ W,
    const float* __restrict__ bias, float* __restrict__ Y,
    int rowb, int mode)
{
    __shared__ __align__(16) float Xs[32 * 136];   // [k][m], pad 136 (==8 mod 32)
    __shared__ __align__(16) float Ws[32 * 136];   // [k][perm(n)], perm=(n&7)*16+(n>>3)

    const int tid  = threadIdx.x;
    const int lane = tid & 31, w = tid >> 5;
    const int g = lane >> 2, t = lane & 3;
    const int mw = (w & 3) * 32;
    const int nhalf = w >> 2;            // 0 or 1
    const int nw = nhalf * 64;

    float o[2][8][4];
#pragma unroll
    for (int mf = 0; mf < 2; mf++)
#pragma unroll
        for (int j = 0; j < 8; j++)
#pragma unroll
            for (int c = 0; c < 4; c++) o[mf][j][c] = 0.f;

    for (int kc = 0; kc < 128; kc += 32) {
        __syncthreads();
        // ---- stage X chunk: warp w owns k-cols kc+4w..kc+4w+3 ----
        {
            const int kg = w;
#pragma unroll
            for (int i = 0; i < 4; i++) {
                int m = lane + 32 * i;
                float4 xv = *(const float4*)&X[(size_t)(rowb + m) * CC + kc + kg * 4];
                float* d = &Xs[(kg * 4) * 136 + m];
                d[0]   = to_tf32(xv.x);
                d[136] = to_tf32(xv.y);
                d[272] = to_tf32(xv.z);
                d[408] = to_tf32(xv.w);
            }
        }
        // ---- stage W chunk (column-permuted) ----
#pragma unroll
        for (int i = 0; i < 4; i++) {
            int v = tid + i * 256;
            int k = v >> 5, ng = v & 31;
            float4 wv = *(const float4*)&W[(size_t)(kc + k) * CC + ng * 4];
            float vals[4] = {to_tf32(wv.x), to_tf32(wv.y), to_tf32(wv.z), to_tf32(wv.w)};
            int n0 = ng * 4;
#pragma unroll
            for (int c = 0; c < 4; c++) {
                int n = n0 + c;
                Ws[k * 136 + (n & 7) * 16 + (n >> 3)] = vals[c];
            }
        }
        __syncthreads();

#pragma unroll
        for (int s = 0; s < 4; s++) {
            const float* xr0 = &Xs[(s * 8 + t) * 136 + mw];
            const float* xr1 = xr0 + 4 * 136;
            float aA0 = xr0[g],      aA1 = xr0[g + 8];
            float aA2 = xr1[g],      aA3 = xr1[g + 8];
            float aB0 = xr0[16 + g], aB1 = xr0[24 + g];
            float aB2 = xr1[16 + g], aB3 = xr1[24 + g];

            const float* wr0 = &Ws[(s * 8 + t) * 136 + g * 16 + nhalf * 8];
            const float* wr1 = wr0 + 4 * 136;
            float4 b0a = *(const float4*)wr0;
            float4 b0b = *(const float4*)(wr0 + 4);
            float4 b1a = *(const float4*)wr1;
            float4 b1b = *(const float4*)(wr1 + 4);
            float bb0[8] = {b0a.x, b0a.y, b0a.z, b0a.w, b0b.x, b0b.y, b0b.z, b0b.w};
            float bb1[8] = {b1a.x, b1a.y, b1a.z, b1a.w, b1b.x, b1b.y, b1b.z, b1b.w};
#pragma unroll
            for (int j = 0; j < 8; j++) {
                mma8(o[0][j], aA0, aA1, aA2, aA3, bb0[j], bb1[j]);
                mma8(o[1][j], aB0, aB1, aB2, aB3, bb0[j], bb1[j]);
            }
        }
    }

    const float qscale = 0.25503486f;   // 32^-0.5 * log2(e)
    if (mode == 0) {
#pragma unroll
        for (int j = 0; j < 8; j++) {
            int col = nw + 8 * j + 2 * t;
            float2 bv = *(const float2*)&bias[col];
#pragma unroll
            for (int mf = 0; mf < 2; mf++) {
                int r0 = rowb + mw + 16 * mf + g;
                *(float2*)&Y[(size_t)r0 * CC + col] =
                    make_float2(o[mf][j][0] + bv.x, o[mf][j][1] + bv.y);
                *(float2*)&Y[(size_t)(r0 + 8) * CC + col] =
                    make_float2(o[mf][j][2] + bv.x, o[mf][j][3] + bv.y);
            }
        }
    } else {
#pragma unroll
        for (int j = 0; j < 8; j++) {
            int col = nw + 8 * j + 2 * t;
            int h = col >> 5;
            int d0 = col & 31, d1 = d0 + 1;
            int dp0 = (d0 & 3) * 8 + (d0 >> 2);
            int dp1 = (d1 & 3) * 8 + (d1 >> 2);
            float bx = bias[col], by = bias[col + 1];
#pragma unroll
            for (int mf = 0; mf < 2; mf++) {
#pragma unroll
                for (int rh = 0; rh < 2; rh++) {
                    int row = rowb + mw + 16 * mf + g + 8 * rh;
                    int bb = row / NQ, n = row - bb * NQ;
                    float* bp = &Y[((size_t)(bb * HEADS + h) * NQ + n) * DH];
                    bp[dp0] = to_tf32((o[mf][j][2 * rh]     + bx) * qscale);
                    bp[dp1] = to_tf32((o[mf][j][2 * rh + 1] + by) * qscale);
                }
            }
        }
    }
}

// fused: q projection (tensor) + spatial-reduction conv
__global__ __launch_bounds__(256) void qproj_conv_kernel(
    const float* __restrict__ x,
    const float* __restrict__ Wq, const float* __restrict__ bq, float* __restrict__ Q,
    const float* __restrict__ cw, const float* __restrict__ cb,
    const float* __restrict__ gamma, const float* __restrict__ beta,
    const float* __restrict__ mean, const float* __restrict__ var,
    float* __restrict__ xr)
{
    if (blockIdx.x < QPB2) {
        proj_mma_body(x, Wq, bq, Q, blockIdx.x * 128, 2);
        return;
    }
    int t = (blockIdx.x - QPB2) * 256 + threadIdx.x;
    if (t >= BB * NKV * CC) return;
    int c = t & (CC - 1);
    int p = (t >> 7) % NKV;
    int b = t / (NKV * CC);
    int oy = p / 28, ox = p % 28;

    const float* xb = x + (size_t)b * NQ * CC;
    float s = 0.f;
#pragma unroll
    for (int i = 0; i < 2; i++)
#pragma unroll
        for (int j = 0; j < 2; j++)
            s += xb[(size_t)((2 * oy + i) * 56 + (2 * ox + j)) * CC + c] * cw[c * 4 + i * 2 + j];
    s += cb[c];
    float iv = gamma[c] * rsqrtf(var[c] + 1e-5f);
    xr[t] = s * iv + (beta[c] - mean[c] * iv);
}

// output projection (tensor)
__global__ __launch_bounds__(256) void oproj_kernel(
    const float* __restrict__ X, const float* __restrict__ W,
    const float* __restrict__ bias, float* __restrict__ Y)
{
    proj_mma_body(X, W, bias, Y, blockIdx.x * 128, 0);
}

// ---------------- fma projection (kv only) ----------------
// mode 1: K (head-split, d-permute, kv-slot permute, tf32)
// mode 4: V (head-split, kv-tile permute Vp[r%4][d][r/4], tf32)
__device__ __forceinline__ void proj_body(
    const float* __restrict__ X, const float* __restrict__ W,
    const float* __restrict__ bias, float* __restrict__ Y,
    int rowb, int M, int RPB, int mode)
{
    __shared__ __align__(16) float Xs[32][66];
    __shared__ __align__(16) float Ws[32][128];

    const int tid   = threadIdx.x;
    const int col_t = tid & 31;
    const int row_t = tid >> 5;

    u64 acc2[4][4];
#pragma unroll
    for (int rp = 0; rp < 4; rp++)
#pragma unroll
        for (int c = 0; c < 4; c++) acc2[rp][c] = 0ULL;

    for (int kc = 0; kc < 128; kc += 32) {
        __syncthreads();
#pragma unroll
        for (int i = 0; i < 8; i++) {
            int idx = tid + i * 256;
            int r = idx >> 5, kk = idx & 31;
            Xs[kk][r] = X[(size_t)(rowb + r) * CC + kc + kk];
        }
#pragma unroll
        for (int i = 0; i < 16; i++) {
            int idx = tid + i * 256;
            int kk = idx >> 7, cc2 = idx & 127;
            Ws[kk][cc2] = W[(size_t)(kc + kk) * CC + cc2];
        }
        __syncthreads();
#pragma unroll
        for (int kk = 0; kk < 32; kk++) {
            float4 wv = *(const float4*)&Ws[kk][col_t * 4];
            u64 wd0 = pack2(wv.x, wv.x);
            u64 wd1 = pack2(wv.y, wv.y);
            u64 wd2 = pack2(wv.z, wv.z);
            u64 wd3 = pack2(wv.w, wv.w);
            const u64* xrow = (const u64*)&Xs[kk][row_t * 8];
#pragma unroll
            for (int rp = 0; rp < 4; rp++) {
                u64 xp = xrow[rp];
                acc2[rp][0] = fma2(xp, wd0, acc2[rp][0]);
                acc2[rp][1] = fma2(xp, wd1, acc2[rp][1]);
                acc2[rp][2] = fma2(xp, wd2, acc2[rp][2]);
                acc2[rp][3] = fma2(xp, wd3, acc2[rp][3]);
            }
        }
    }

    const int col0 = col_t * 4;
    float4 bv = *(const float4*)&bias[col0];
#pragma unroll
    for (int rp = 0; rp < 4; rp++) {
        float lo[4], hi[4];
#pragma unroll
        for (int c = 0; c < 4; c++) unpack2(acc2[rp][c], lo[c], hi[c]);
        int row0 = rowb + row_t * 8 + 2 * rp;
#pragma unroll
        for (int half = 0; half < 2; half++) {
            int row = row0 + half;
            if (row >= M) continue;
            float* s = half ? hi : lo;
            float o[4];
            o[0] = s[0] + bv.x; o[1] = s[1] + bv.y;
            o[2] = s[2] + bv.z; o[3] = s[3] + bv.w;
            int b = row / RPB, n = row % RPB;
            int h = col0 >> 5, dbase = col0 & 31;
            if (mode == 4) {
                int tile = n >> 6, rr = n & 63;
                float* bp = &Y[(size_t)(b * HEADS + h) * VSTRIDE
                               + tile * 2048 + (rr & 3) * 512 + (rr >> 2)];
#pragma unroll
                for (int i = 0; i < 4; i++)
                    bp[(dbase + i) * 16] = to_tf32(o[i]);
            } else {
                int n2 = (n & ~7) | (((n & 3) << 1) | ((n & 7) >> 2));
                float* bp = &Y[((size_t)(b * HEADS + h) * RPB + n2) * DH];
#pragma unroll
                for (int i = 0; i < 4; i++) {
                    int d = dbase + i;
                    int dp = (d & 3) * 8 + (d >> 2);
                    bp[dp] = to_tf32(o[i]);
                }
            }
        }
    }
}

__global__ __launch_bounds__(256) void proj_kv_kernel(
    const float* __restrict__ X,
    const float* __restrict__ Wk, const float* __restrict__ bk, float* __restrict__ K,
    const float* __restrict__ Wv, const float* __restrict__ bv, float* __restrict__ V,
    int M, int RPB)
{
    int nb = gridDim.x >> 1;
    int half = blockIdx.x >= nb;
    int rowb = (blockIdx.x - (half ? nb : 0)) * 64;
    if (half) proj_body(X, Wv, bv, V, rowb, M, RPB, 4);
    else      proj_body(X, Wk, bk, K, rowb, M, RPB, 1);
}

// ---------------- mma attention (register-resident P) ----------------
#define VS_F    4608
#define SMEM_F  8736

template<int NF>
__device__ __forceinline__ void tile_body(
    const float* __restrict__ Ksm, const float* __restrict__ Vsm,
    const float (&qreg)[4][8], float (&o)[2][4][4], float (&sums)[4],
    const float* const (&rpr)[4], int ktile, int g, int t)
{
    const float L2E = 1.4426950408889634f;
#pragma unroll
    for (int c8 = 0; c8 < NF; c8++) {
        const float* kp = Ksm + (8 * c8 + g) * 36 + t * 8;
        float4 k0 = *(const float4*)kp;
        float4 k1 = *(const float4*)(kp + 4);
        float kb[8] = {k0.x, k0.y, k0.z, k0.w, k1.x, k1.y, k1.z, k1.w};
        float c0[4] = {0.f, 0.f, 0.f, 0.f};
        float c1[4] = {0.f, 0.f, 0.f, 0.f};
#pragma unroll
        for (int s = 0; s < 4; s++) {
            mma8(c0, qreg[0][2*s], qreg[1][2*s], qreg[0][2*s+1], qreg[1][2*s+1],
                 kb[2*s], kb[2*s+1]);
            mma8(c1, qreg[2][2*s], qreg[3][2*s], qreg[2][2*s+1], qreg[3][2*s+1],
                 kb[2*s], kb[2*s+1]);
        }
        int off = ktile + 8 * c8;
        float b00 = rpr[0][off + t], b01 = rpr[0][off + t + 4];
        float b10 = rpr[1][off + t], b11 = rpr[1][off + t + 4];
        float b20 = rpr[2][off + t], b21 = rpr[2][off + t + 4];
        float b30 = rpr[3][off + t], b31 = rpr[3][off + t + 4];
        float p00 = to_tf32(ex2(fmaf(b00, L2E, c0[0])));
        float p02 = to_tf32(ex2(fmaf(b01, L2E, c0[1])));
        float p10 = to_tf32(ex2(fmaf(b10, L2E, c0[2])));
        float p12 = to_tf32(ex2(fmaf(b11, L2E, c0[3])));
        float p20 = to_tf32(ex2(fmaf(b20, L2E, c1[0])));
        float p22 = to_tf32(ex2(fmaf(b21, L2E, c1[1])));
        float p30 = to_tf32(ex2(fmaf(b30, L2E, c1[2])));
        float p32 = to_tf32(ex2(fmaf(b31, L2E, c1[3])));
        sums[0] += p00 + p02; sums[1] += p10 + p12;
        sums[2] += p20 + p22; sums[3] += p30 + p32;
        const int posw = (c8 & 1) << 1;
        const int rh   = c8 >> 1;
#pragma unroll
        for (int nf = 0; nf < 4; nf++) {
            int d  = 8 * nf + g;
            int cc = ((d << 2) + rh) ^ ((d >> 1) & 3);
            float2 bv = *(const float2*)(Vsm + t * 516 + 4 * cc + posw);
            mma8(o[0][nf], p00, p10, p02, p12, bv.x, bv.y);
            mma8(o[1][nf], p20, p30, p22, p32, bv.x, bv.y);
        }
    }
}

__global__ __launch_bounds__(128, 3) void attn_mma_kernel(
    const float* __restrict__ q, const float* __restrict__ k, const float* __restrict__ v,
    const float* __restrict__ relpos, float* __restrict__ out)
{
    __shared__ __align__(16) float dsm[SMEM_F];

    const int b   = blockIdx.z;
    const int h   = blockIdx.y;
    const int qt  = blockIdx.x;
    const int tid = threadIdx.x;
    const int lane = tid & 31, w = tid >> 5;
    const int g = lane >> 2, t = lane & 3;
    const int q0 = qt * 128;

    const float* qb = q + (size_t)(b * HEADS + h) * NQ * DH;
    const float* kb = k + (size_t)(b * HEADS + h) * NKV * DH;
    const float* vb = v + (size_t)(b * HEADS + h) * VSTRIDE;

    float qreg[4][8];
    int qraw[4];
    const float* rpr[4];
#pragma unroll
    for (int rr = 0; rr < 4; rr++) {
        int qg = q0 + 32 * w + g + 8 * rr;
        qraw[rr] = qg;
        if (qg >= NQ) qg = NQ - 1;
        const float* qp = qb + (size_t)qg * DH + t * 8;
        float4 x0 = *(const float4*)qp;
        float4 x1 = *(const float4*)(qp + 4);
        qreg[rr][0] = x0.x; qreg[rr][1] = x0.y; qreg[rr][2] = x0.z; qreg[rr][3] = x0.w;
        qreg[rr][4] = x1.x; qreg[rr][5] = x1.y; qreg[rr][6] = x1.z; qreg[rr][7] = x1.w;
        rpr[rr] = relpos + ((size_t)h * NQ + qg) * NKV;
    }

    float o[2][4][4];
#pragma unroll
    for (int i = 0; i < 2; i++)
#pragma unroll
        for (int j = 0; j < 4; j++)
#pragma unroll
            for (int c = 0; c < 4; c++) o[i][j][c] = 0.f;
    float sums[4] = {0.f, 0.f, 0.f, 0.f};

    const unsigned kd_base = smem_u32(dsm);
    const unsigned vd_base = smem_u32(dsm + VS_F);

    {
#pragma unroll
        for (int i = 0; i < 8; i++) {
            int idx = tid + i * 128;
            if (idx < 512) {
                int r = idx >> 3, c = idx & 7;
                cp16(kd_base + r * 144 + c * 16, kb + idx * 4);
            } else {
                int j = idx - 512;
                int dst = (j >> 7) * 129 + ((j & 127) ^ ((j >> 3) & 3));
                cp16(vd_base + dst * 16, vb + j * 4);
            }
        }
    }
    cp_commit();

    for (int tt = 0; tt < 13; tt++) {
        const int buf = tt & 1;
        cp_wait0();
        __syncthreads();

        if (tt + 1 < 13) {
            const int nb = buf ^ 1;
            const unsigned kd = kd_base + nb * 9216;
            const unsigned vd = vd_base + nb * 8256;
            const float* kg = kb + (size_t)(tt + 1) * 2048;
            const float* vg = vb + (size_t)(tt + 1) * 2048;
            if (tt + 1 < NFULL) {
#pragma unroll
                for (int i = 0; i < 8; i++) {
                    int idx = tid + i * 128;
                    if (idx < 512) {
                        int r = idx >> 3, c = idx & 7;
                        cp16(kd + r * 144 + c * 16, kg + idx * 4);
                    } else {
                        int j = idx - 512;
                        int dst = (j >> 7) * 129 + ((j & 127) ^ ((j >> 3) & 3));
                        cp16(vd + dst * 16, vg + j * 4);
                    }
                }
            } else {
#pragma unroll
                for (int i = 0; i < 2; i++) {
                    int idx = tid + i * 128;
                    if (idx < 128) {
                        int r = idx >> 3, c = idx & 7;
                        cp16(kd + r * 144 + c * 16, kg + idx * 4);
                    } else {
                        int j = idx - 128;
                        int grp = j >> 5, d = j & 31;
                        int dst = grp * 129 + ((d << 2) ^ ((d >> 1) & 3));
                        cp16(vd + dst * 16, vg + grp * 512 + d * 16);
                    }
                }
            }
        }
        cp_commit();

        const float* Ksm = dsm + buf * 2304;
        const float* Vsm = dsm + VS_F + buf * 2064;
        if (tt < NFULL)
            tile_body<8>(Ksm, Vsm, qreg, o, sums, rpr, tt * TN, g, t);
        else
            tile_body<2>(Ksm, Vsm, qreg, o, sums, rpr, tt * TN, g, t);
    }

    float inv[4];
#pragma unroll
    for (int rr = 0; rr < 4; rr++) {
        float s = sums[rr];
        s += __shfl_xor_sync(0xffffffffu, s, 1);
        s += __shfl_xor_sync(0xffffffffu, s, 2);
        inv[rr] = 1.f / s;
    }
#pragma unroll
    for (int mf = 0; mf < 2; mf++) {
#pragma unroll
        for (int rh = 0; rh < 2; rh++) {
            int rr = 2 * mf + rh;
            int qg = qraw[rr];
            if (qg >= NQ) continue;
            float* op = out + ((size_t)(b * NQ + qg)) * CC + h * 32 + 2 * t;
#pragma unroll
            for (int nf = 0; nf < 4; nf++) {
                float2 val = make_float2(o[mf][nf][2 * rh] * inv[rr],
                                         o[mf][nf][2 * rh + 1] * inv[rr]);
                *(float2*)(op + 8 * nf) = val;
            }
        }
    }
}

// ---------------- launch ----------------
extern "C" void kernel_launch(void* const* d_in, const int* in_sizes, int n_in,
                              void* d_out, int out_size)
{
    const float* x      = (const float*)d_in[0];
    const float* relpos = (const float*)d_in[1];
    const float* Wq     = (const float*)d_in[2];
    const float* bq     = (const float*)d_in[3];
    const float* Wk     = (const float*)d_in[4];
    const float* bk     = (const float*)d_in[5];
    const float* Wv     = (const float*)d_in[6];
    const float* bv     = (const float*)d_in[7];
    const float* cw     = (const float*)d_in[8];
    const float* cb     = (const float*)d_in[9];
    const float* gamma  = (const float*)d_in[10];
    const float* beta   = (const float*)d_in[11];
    const float* mean   = (const float*)d_in[12];
    const float* var    = (const float*)d_in[13];
    const float* Wp     = (const float*)d_in[14];
    const float* bp     = (const float*)d_in[15];
    float* out = (float*)d_out;

    float *q, *k, *v, *xr, *ao;
    cudaGetSymbolAddress((void**)&q,  g_q);
    cudaGetSymbolAddress((void**)&k,  g_k);
    cudaGetSymbolAddress((void**)&v,  g_v);
    cudaGetSymbolAddress((void**)&xr, g_xr);
    cudaGetSymbolAddress((void**)&ao, g_ao);

    // 1) fused q projection (tensor mma) + spatial-reduction conv
    int conv_blocks = (BB * NKV * CC + 255) / 256;
    qproj_conv_kernel<<<QPB2 + conv_blocks, 256>>>(x, Wq, bq, q,
                                                   cw, cb, gamma, beta, mean, var, xr);
    // 2) fused k+v projections (fma path; K d+slot-permuted tf32; V tile-permuted tf32)
    proj_kv_kernel<<<2 * (BB * NKV) / 64, 256>>>(xr, Wk, bk, k, Wv, bv, v, BB * NKV, NKV);
    // 3) attention: tensor-core tf32 mma, register-resident P
    dim3 ag((NQ + 127) / 128, HEADS, BB);
    attn_mma_kernel<<<ag, 128>>>(q, k, v, relpos, ao);
    // 4) output projection (tensor mma)
    oproj_kernel<<<QPB2, 256>>>(ao, Wp, bp, out);
}

// round 9
// speedup vs baseline: 1.2252x; 1.0961x over previous
#include <cuda_runtime.h>
#include <cstdint>

// ---------------- problem constants ----------------
#define BB      8
#define HEADS   4
#define NQ      3136
#define NKV     784
#define DH      32
#define CC      128
#define TN      64                 // kv tile (12 full tiles + tail of 16)
#define NFULL   12
#define VSTRIDE 26624              // 13 tiles * 2048 floats per (b,h)
#define QPB2    ((BB * NQ) / 128)  // mma-proj blocks = 196

typedef unsigned long long u64;

// ---------------- scratch (device globals; no allocation) ----------------
__device__ float g_q [BB * HEADS * NQ  * DH];      // permuted d', tf32, scaled by 32^-.5*log2e
__device__ float g_k [BB * HEADS * NKV * DH];      // permuted d', tf32 (NO kv-slot permute)
__device__ float g_v [BB * HEADS * VSTRIDE];       // sigma-permuted Vp, tf32
__device__ float g_xr[BB * NKV * CC];
__device__ float g_ao[BB * NQ  * CC];

// ---------------- helpers ----------------
__device__ __forceinline__ u64 pack2(float x, float y) {
    u64 r; asm("mov.b64 %0, {%1, %2};" : "=l"(r) : "f"(x), "f"(y)); return r;
}
__device__ __forceinline__ void unpack2(u64 v, float& x, float& y) {
    asm("mov.b64 {%0, %1}, %2;" : "=f"(x), "=f"(y) : "l"(v));
}
__device__ __forceinline__ u64 fma2(u64 a, u64 b, u64 c) {
    u64 d; asm("fma.rn.f32x2 %0, %1, %2, %3;" : "=l"(d) : "l"(a), "l"(b), "l"(c)); return d;
}
__device__ __forceinline__ float to_tf32(float x) {
    float r; asm("cvt.rna.tf32.f32 %0, %1;" : "=f"(r) : "f"(x)); return r;
}
__device__ __forceinline__ float ex2(float x) {
    float r; asm("ex2.approx.f32 %0, %1;" : "=f"(r) : "f"(x)); return r;
}
__device__ __forceinline__ unsigned smem_u32(const void* p) {
    return (unsigned)__cvta_generic_to_shared(p);
}
__device__ __forceinline__ void cp16(unsigned dst, const void* src) {
    asm volatile("cp.async.cg.shared.global [%0], [%1], 16;\n" :: "r"(dst), "l"(src));
}
__device__ __forceinline__ void cp_commit() {
    asm volatile("cp.async.commit_group;\n" ::: "memory");
}
__device__ __forceinline__ void cp_wait0() {
    asm volatile("cp.async.wait_group 0;\n" ::: "memory");
}

// mma.sync m16n8k8 tf32 (base PTX, sm_80+)
__device__ __forceinline__ void mma8(float c[4], float a0, float a1, float a2, float a3,
                                     float b0, float b1) {
    asm volatile(
        "mma.sync.aligned.m16n8k8.row.col.f32.tf32.tf32.f32 "
        "{%0,%1,%2,%3}, {%4,%5,%6,%7}, {%8,%9}, {%0,%1,%2,%3};"
        : "+f"(c[0]), "+f"(c[1]), "+f"(c[2]), "+f"(c[3])
        : "r"(__float_as_uint(a0)), "r"(__float_as_uint(a1)),
          "r"(__float_as_uint(a2)), "r"(__float_as_uint(a3)),
          "r"(__float_as_uint(b0)), "r"(__float_as_uint(b1)));
}

// ---------------- tensor-core projection: Y = X(Mx128) @ W(128x128) + b ----
// CTA = 128x128 tile, 8 warps (4m x 2n), K chunks of 32, software-pipelined
// register staging (next chunk's LDGs overlap current chunk's MMAs).
// mode 0: plain fp32 row-major out.  mode 2: Q out (head-split, d-permute,
// tf32, scaled by 32^-0.5 * log2e).
__device__ __forceinline__ void proj_mma_body(
    const float* __restrict__ X, const float* __restrict__ W,
    const float* __restrict__ bias, float* __restrict__ Y,
    int rowb, int mode)
{
    __shared__ __align__(16) float Xs[32 * 136];   // [k][m], pad 136
    __shared__ __align__(16) float Ws[32 * 136];   // [k][perm(n)], perm=(n&7)*16+(n>>3)

    const int tid  = threadIdx.x;
    const int lane = tid & 31, w = tid >> 5;
    const int g = lane >> 2, t = lane & 3;
    const int mw = (w & 3) * 32;
    const int nhalf = w >> 2;
    const int nw = nhalf * 64;

    float o[2][8][4];
#pragma unroll
    for (int mf = 0; mf < 2; mf++)
#pragma unroll
        for (int j = 0; j < 8; j++)
#pragma unroll
            for (int c = 0; c < 4; c++) o[mf][j][c] = 0.f;

    float4 xa[4], wa[4];
    auto load_chunk = [&](int kc) {
#pragma unroll
        for (int i = 0; i < 4; i++) {
            int m = lane + 32 * i;
            xa[i] = *(const float4*)&X[(size_t)(rowb + m) * CC + kc + w * 4];
        }
#pragma unroll
        for (int i = 0; i < 4; i++) {
            int vv = tid + i * 256;
            int kk = vv >> 5, ng = vv & 31;
            wa[i] = *(const float4*)&W[(size_t)(kc + kk) * CC + ng * 4];
        }
    };

    load_chunk(0);
    for (int c = 0; c < 4; c++) {
        // ---- store staged chunk to smem (tf32-rounded) ----
#pragma unroll
        for (int i = 0; i < 4; i++) {
            int m = lane + 32 * i;
            float* d = &Xs[(w * 4) * 136 + m];
            d[0]   = to_tf32(xa[i].x);
            d[136] = to_tf32(xa[i].y);
            d[272] = to_tf32(xa[i].z);
            d[408] = to_tf32(xa[i].w);
        }
#pragma unroll
        for (int i = 0; i < 4; i++) {
            int vv = tid + i * 256;
            int kk = vv >> 5, n0 = (vv & 31) * 4;
            float vals[4] = {to_tf32(wa[i].x), to_tf32(wa[i].y),
                             to_tf32(wa[i].z), to_tf32(wa[i].w)};
#pragma unroll
            for (int c2 = 0; c2 < 4; c2++) {
                int n = n0 + c2;
                Ws[kk * 136 + (n & 7) * 16 + (n >> 3)] = vals[c2];
            }
        }
        __syncthreads();
        if (c < 3) load_chunk((c + 1) * 32);   // overlap LDG with mma below

#pragma unroll
        for (int s = 0; s < 4; s++) {
            const float* xr0 = &Xs[(s * 8 + t) * 136 + mw];
            const float* xr1 = xr0 + 4 * 136;
            float aA0 = xr0[g],      aA1 = xr0[g + 8];
            float aA2 = xr1[g],      aA3 = xr1[g + 8];
            float aB0 = xr0[16 + g], aB1 = xr0[24 + g];
            float aB2 = xr1[16 + g], aB3 = xr1[24 + g];

            const float* wr0 = &Ws[(s * 8 + t) * 136 + g * 16 + nhalf * 8];
            const float* wr1 = wr0 + 4 * 136;
            float4 b0a = *(const float4*)wr0;
            float4 b0b = *(const float4*)(wr0 + 4);
            float4 b1a = *(const float4*)wr1;
            float4 b1b = *(const float4*)(wr1 + 4);
            float bb0[8] = {b0a.x, b0a.y, b0a.z, b0a.w, b0b.x, b0b.y, b0b.z, b0b.w};
            float bb1[8] = {b1a.x, b1a.y, b1a.z, b1a.w, b1b.x, b1b.y, b1b.z, b1b.w};
#pragma unroll
            for (int j = 0; j < 8; j++) {
                mma8(o[0][j], aA0, aA1, aA2, aA3, bb0[j], bb1[j]);
                mma8(o[1][j], aB0, aB1, aB2, aB3, bb0[j], bb1[j]);
            }
        }
        __syncthreads();
    }

    const float qscale = 0.25503486f;   // 32^-0.5 * log2(e)
    if (mode == 0) {
#pragma unroll
        for (int j = 0; j < 8; j++) {
            int col = nw + 8 * j + 2 * t;
            float2 bv = *(const float2*)&bias[col];
#pragma unroll
            for (int mf = 0; mf < 2; mf++) {
                int r0 = rowb + mw + 16 * mf + g;
                *(float2*)&Y[(size_t)r0 * CC + col] =
                    make_float2(o[mf][j][0] + bv.x, o[mf][j][1] + bv.y);
                *(float2*)&Y[(size_t)(r0 + 8) * CC + col] =
                    make_float2(o[mf][j][2] + bv.x, o[mf][j][3] + bv.y);
            }
        }
    } else {
#pragma unroll
        for (int j = 0; j < 8; j++) {
            int col = nw + 8 * j + 2 * t;
            int h = col >> 5;
            int d0 = col & 31, d1 = d0 + 1;
            int dp0 = (d0 & 3) * 8 + (d0 >> 2);
            int dp1 = (d1 & 3) * 8 + (d1 >> 2);
            float bx = bias[col], by = bias[col + 1];
#pragma unroll
            for (int mf = 0; mf < 2; mf++) {
#pragma unroll
                for (int rh = 0; rh < 2; rh++) {
                    int row = rowb + mw + 16 * mf + g + 8 * rh;
                    int bb = row / NQ, n = row - bb * NQ;
                    float* bp = &Y[((size_t)(bb * HEADS + h) * NQ + n) * DH];
                    bp[dp0] = to_tf32((o[mf][j][2 * rh]     + bx) * qscale);
                    bp[dp1] = to_tf32((o[mf][j][2 * rh + 1] + by) * qscale);
                }
            }
        }
    }
}

// fused: q projection (tensor) + spatial-reduction conv
__global__ __launch_bounds__(256) void qproj_conv_kernel(
    const float* __restrict__ x,
    const float* __restrict__ Wq, const float* __restrict__ bq, float* __restrict__ Q,
    const float* __restrict__ cw, const float* __restrict__ cb,
    const float* __restrict__ gamma, const float* __restrict__ beta,
    const float* __restrict__ mean, const float* __restrict__ var,
    float* __restrict__ xr)
{
    if (blockIdx.x < QPB2) {
        proj_mma_body(x, Wq, bq, Q, blockIdx.x * 128, 2);
        return;
    }
    int t = (blockIdx.x - QPB2) * 256 + threadIdx.x;
    if (t >= BB * NKV * CC) return;
    int c = t & (CC - 1);
    int p = (t >> 7) % NKV;
    int b = t / (NKV * CC);
    int oy = p / 28, ox = p % 28;

    const float* xb = x + (size_t)b * NQ * CC;
    float s = 0.f;
#pragma unroll
    for (int i = 0; i < 2; i++)
#pragma unroll
        for (int j = 0; j < 2; j++)
            s += xb[(size_t)((2 * oy + i) * 56 + (2 * ox + j)) * CC + c] * cw[c * 4 + i * 2 + j];
    s += cb[c];
    float iv = gamma[c] * rsqrtf(var[c] + 1e-5f);
    xr[t] = s * iv + (beta[c] - mean[c] * iv);
}

// output projection (tensor)
__global__ __launch_bounds__(256) void oproj_kernel(
    const float* __restrict__ X, const float* __restrict__ W,
    const float* __restrict__ bias, float* __restrict__ Y)
{
    proj_mma_body(X, W, bias, Y, blockIdx.x * 128, 0);
}

// ---------------- fma projection (kv only) ----------------
// mode 1: K (head-split, d-permute, tf32) — NO kv-slot permute
// mode 4: V (head-split, sigma-permute: kv n -> chunkrow (n&7)>>1,
//            offset 2*(n>>3)+(n&1), tf32)
__device__ __forceinline__ void proj_body(
    const float* __restrict__ X, const float* __restrict__ W,
    const float* __restrict__ bias, float* __restrict__ Y,
    int rowb, int M, int RPB, int mode)
{
    __shared__ __align__(16) float Xs[32][66];
    __shared__ __align__(16) float Ws[32][128];

    const int tid   = threadIdx.x;
    const int col_t = tid & 31;
    const int row_t = tid >> 5;

    u64 acc2[4][4];
#pragma unroll
    for (int rp = 0; rp < 4; rp++)
#pragma unroll
        for (int c = 0; c < 4; c++) acc2[rp][c] = 0ULL;

    for (int kc = 0; kc < 128; kc += 32) {
        __syncthreads();
#pragma unroll
        for (int i = 0; i < 8; i++) {
            int idx = tid + i * 256;
            int r = idx >> 5, kk = idx & 31;
            Xs[kk][r] = X[(size_t)(rowb + r) * CC + kc + kk];
        }
#pragma unroll
        for (int i = 0; i < 16; i++) {
            int idx = tid + i * 256;
            int kk = idx >> 7, cc2 = idx & 127;
            Ws[kk][cc2] = W[(size_t)(kc + kk) * CC + cc2];
        }
        __syncthreads();
#pragma unroll
        for (int kk = 0; kk < 32; kk++) {
            float4 wv = *(const float4*)&Ws[kk][col_t * 4];
            u64 wd0 = pack2(wv.x, wv.x);
            u64 wd1 = pack2(wv.y, wv.y);
            u64 wd2 = pack2(wv.z, wv.z);
            u64 wd3 = pack2(wv.w, wv.w);
            const u64* xrow = (const u64*)&Xs[kk][row_t * 8];
#pragma unroll
            for (int rp = 0; rp < 4; rp++) {
                u64 xp = xrow[rp];
                acc2[rp][0] = fma2(xp, wd0, acc2[rp][0]);
                acc2[rp][1] = fma2(xp, wd1, acc2[rp][1]);
                acc2[rp][2] = fma2(xp, wd2, acc2[rp][2]);
                acc2[rp][3] = fma2(xp, wd3, acc2[rp][3]);
            }
        }
    }

    const int col0 = col_t * 4;
    float4 bv = *(const float4*)&bias[col0];
#pragma unroll
    for (int rp = 0; rp < 4; rp++) {
        float lo[4], hi[4];
#pragma unroll
        for (int c = 0; c < 4; c++) unpack2(acc2[rp][c], lo[c], hi[c]);
        int row0 = rowb + row_t * 8 + 2 * rp;
#pragma unroll
        for (int half = 0; half < 2; half++) {
            int row = row0 + half;
            if (row >= M) continue;
            float* s = half ? hi : lo;
            float o[4];
            o[0] = s[0] + bv.x; o[1] = s[1] + bv.y;
            o[2] = s[2] + bv.z; o[3] = s[3] + bv.w;
            int b = row / RPB, n = row % RPB;
            int h = col0 >> 5, dbase = col0 & 31;
            if (mode == 4) {
                int tile = n >> 6, rr = n & 63;
                int off = ((rr & 7) >> 1) * 512 + 2 * (rr >> 3) + (rr & 1);
                float* bp = &Y[(size_t)(b * HEADS + h) * VSTRIDE + tile * 2048 + off];
#pragma unroll
                for (int i = 0; i < 4; i++)
                    bp[(dbase + i) * 16] = to_tf32(o[i]);
            } else {
                float* bp = &Y[((size_t)(b * HEADS + h) * RPB + n) * DH];
#pragma unroll
                for (int i = 0; i < 4; i++) {
                    int d = dbase + i;
                    int dp = (d & 3) * 8 + (d >> 2);
                    bp[dp] = to_tf32(o[i]);
                }
            }
        }
    }
}

__global__ __launch_bounds__(256) void proj_kv_kernel(
    const float* __restrict__ X,
    const float* __restrict__ Wk, const float* __restrict__ bk, float* __restrict__ K,
    const float* __restrict__ Wv, const float* __restrict__ bv, float* __restrict__ V,
    int M, int RPB)
{
    int nb = gridDim.x >> 1;
    int half = blockIdx.x >= nb;
    int rowb = (blockIdx.x - (half ? nb : 0)) * 64;
    if (half) proj_body(X, Wv, bv, V, rowb, M, RPB, 4);
    else      proj_body(X, Wk, bk, K, rowb, M, RPB, 1);
}

// ---------------- mma attention (register-resident P, prefetched bias) ----
#define VS_F    4608
#define SMEM_F  8736

template<int NF>
__device__ __forceinline__ void tile_body(
    const float* __restrict__ Ksm, const float* __restrict__ Vsm,
    const float (&qreg)[4][8], float (&o)[2][4][4], float (&sums)[4],
    const float* const (&rpr)[4], int ktile, int g, int t)
{
    const float L2E = 1.4426950408889634f;
    // prefetch bias chunk 0: float2 = kv (2t, 2t+1) per fragment row
    float2 bb[4];
#pragma unroll
    for (int rr = 0; rr < 4; rr++)
        bb[rr] = *(const float2*)(rpr[rr] + ktile + 2 * t);

#pragma unroll
    for (int c8 = 0; c8 < NF; c8++) {
        float2 nb[4];
        if (c8 + 1 < NF) {
#pragma unroll
            for (int rr = 0; rr < 4; rr++)
                nb[rr] = *(const float2*)(rpr[rr] + ktile + 8 * (c8 + 1) + 2 * t);
        }
        // ---- S chunk = Q @ K^T (original kv order; C cols = kv 2t, 2t+1) ----
        const float* kp = Ksm + (8 * c8 + g) * 36 + t * 8;
        float4 k0 = *(const float4*)kp;
        float4 k1 = *(const float4*)(kp + 4);
        float kb[8] = {k0.x, k0.y, k0.z, k0.w, k1.x, k1.y, k1.z, k1.w};
        float c0[4] = {0.f, 0.f, 0.f, 0.f};
        float c1[4] = {0.f, 0.f, 0.f, 0.f};
#pragma unroll
        for (int s = 0; s < 4; s++) {
            mma8(c0, qreg[0][2*s], qreg[1][2*s], qreg[0][2*s+1], qreg[1][2*s+1],
                 kb[2*s], kb[2*s+1]);
            mma8(c1, qreg[2][2*s], qreg[3][2*s], qreg[2][2*s+1], qreg[3][2*s+1],
                 kb[2*s], kb[2*s+1]);
        }
        // ---- exp2(S + bias) -> P (registers), accumulate sums ----
        float p00 = to_tf32(ex2(fmaf(bb[0].x, L2E, c0[0])));   // row g,   kv 2t
        float p02 = to_tf32(ex2(fmaf(bb[0].y, L2E, c0[1])));   // row g,   kv 2t+1
        float p10 = to_tf32(ex2(fmaf(bb[1].x, L2E, c0[2])));   // row g+8, kv 2t
        float p12 = to_tf32(ex2(fmaf(bb[1].y, L2E, c0[3])));
        float p20 = to_tf32(ex2(fmaf(bb[2].x, L2E, c1[0])));
        float p22 = to_tf32(ex2(fmaf(bb[2].y, L2E, c1[1])));
        float p30 = to_tf32(ex2(fmaf(bb[3].x, L2E, c1[2])));
        float p32 = to_tf32(ex2(fmaf(bb[3].y, L2E, c1[3])));
        sums[0] += p00 + p02; sums[1] += p10 + p12;
        sums[2] += p20 + p22; sums[3] += p30 + p32;
#pragma unroll
        for (int rr = 0; rr < 4; rr++) bb[rr] = nb[rr];
        // ---- O += P @ V (V sigma-permuted: B k-row t <-> kv 8c8+2t,
        //      k-row t+4 <-> kv 8c8+2t+1; A frags direct from registers) ----
        const int posw = (c8 & 1) << 1;
        const int rh   = c8 >> 1;
#pragma unroll
        for (int nf = 0; nf < 4; nf++) {
            int d  = 8 * nf + g;
            int cc = ((d << 2) + rh) ^ ((d >> 1) & 3);
            float2 bv = *(const float2*)(Vsm + t * 516 + 4 * cc + posw);
            mma8(o[0][nf], p00, p10, p02, p12, bv.x, bv.y);
            mma8(o[1][nf], p20, p30, p22, p32, bv.x, bv.y);
        }
    }
}

__global__ __launch_bounds__(128, 3) void attn_mma_kernel(
    const float* __restrict__ q, const float* __restrict__ k, const float* __restrict__ v,
    const float* __restrict__ relpos, float* __restrict__ out)
{
    __shared__ __align__(16) float dsm[SMEM_F];

    const int b   = blockIdx.z;
    const int h   = blockIdx.y;
    const int qt  = blockIdx.x;
    const int tid = threadIdx.x;
    const int lane = tid & 31, w = tid >> 5;
    const int g = lane >> 2, t = lane & 3;
    const int q0 = qt * 128;

    const float* qb = q + (size_t)(b * HEADS + h) * NQ * DH;
    const float* kb = k + (size_t)(b * HEADS + h) * NKV * DH;
    const float* vb = v + (size_t)(b * HEADS + h) * VSTRIDE;

    float qreg[4][8];
    int qraw[4];
    const float* rpr[4];
#pragma unroll
    for (int rr = 0; rr < 4; rr++) {
        int qg = q0 + 32 * w + g + 8 * rr;
        qraw[rr] = qg;
        if (qg >= NQ) qg = NQ - 1;
        const float* qp = qb + (size_t)qg * DH + t * 8;
        float4 x0 = *(const float4*)qp;
        float4 x1 = *(const float4*)(qp + 4);
        qreg[rr][0] = x0.x; qreg[rr][1] = x0.y; qreg[rr][2] = x0.z; qreg[rr][3] = x0.w;
        qreg[rr][4] = x1.x; qreg[rr][5] = x1.y; qreg[rr][6] = x1.z; qreg[rr][7] = x1.w;
        rpr[rr] = relpos + ((size_t)h * NQ + qg) * NKV;
    }

    float o[2][4][4];
#pragma unroll
    for (int i = 0; i < 2; i++)
#pragma unroll
        for (int j = 0; j < 4; j++)
#pragma unroll
            for (int c = 0; c < 4; c++) o[i][j][c] = 0.f;
    float sums[4] = {0.f, 0.f, 0.f, 0.f};

    const unsigned kd_base = smem_u32(dsm);
    const unsigned vd_base = smem_u32(dsm + VS_F);

    {
#pragma unroll
        for (int i = 0; i < 8; i++) {
            int idx = tid + i * 128;
            if (idx < 512) {
                int r = idx >> 3, c = idx & 7;
                cp16(kd_base + r * 144 + c * 16, kb + idx * 4);
            } else {
                int j = idx - 512;
                int dst = (j >> 7) * 129 + ((j & 127) ^ ((j >> 3) & 3));
                cp16(vd_base + dst * 16, vb + j * 4);
            }
        }
    }
    cp_commit();

    for (int tt = 0; tt < 13; tt++) {
        const int buf = tt & 1;
        cp_wait0();
        __syncthreads();

        if (tt + 1 < 13) {
            const int nb = buf ^ 1;
            const unsigned kd = kd_base + nb * 9216;
            const unsigned vd = vd_base + nb * 8256;
            const float* kg = kb + (size_t)(tt + 1) * 2048;
            const float* vg = vb + (size_t)(tt + 1) * 2048;
            if (tt + 1 < NFULL) {
#pragma unroll
                for (int i = 0; i < 8; i++) {
                    int idx = tid + i * 128;
                    if (idx < 512) {
                        int r = idx >> 3, c = idx & 7;
                        cp16(kd + r * 144 + c * 16, kg + idx * 4);
                    } else {
                        int j = idx - 512;
                        int dst = (j >> 7) * 129 + ((j & 127) ^ ((j >> 3) & 3));
                        cp16(vd + dst * 16, vg + j * 4);
                    }
                }
            } else {
#pragma unroll
                for (int i = 0; i < 2; i++) {
                    int idx = tid + i * 128;
                    if (idx < 128) {
                        int r = idx >> 3, c = idx & 7;
                        cp16(kd + r * 144 + c * 16, kg + idx * 4);
                    } else {
                        int j = idx - 128;
                        int grp = j >> 5, d = j & 31;
                        int dst = grp * 129 + ((d << 2) ^ ((d >> 1) & 3));
                        cp16(vd + dst * 16, vg + grp * 512 + d * 16);
                    }
                }
            }
        }
        cp_commit();

        const float* Ksm = dsm + buf * 2304;
        const float* Vsm = dsm + VS_F + buf * 2064;
        if (tt < NFULL)
            tile_body<8>(Ksm, Vsm, qreg, o, sums, rpr, tt * TN, g, t);
        else
            tile_body<2>(Ksm, Vsm, qreg, o, sums, rpr, tt * TN, g, t);
    }

    float inv[4];
#pragma unroll
    for (int rr = 0; rr < 4; rr++) {
        float s = sums[rr];
        s += __shfl_xor_sync(0xffffffffu, s, 1);
        s += __shfl_xor_sync(0xffffffffu, s, 2);
        inv[rr] = 1.f / s;
    }
#pragma unroll
    for (int mf = 0; mf < 2; mf++) {
#pragma unroll
        for (int rh = 0; rh < 2; rh++) {
            int rr = 2 * mf + rh;
            int qg = qraw[rr];
            if (qg >= NQ) continue;
            float* op = out + ((size_t)(b * NQ + qg)) * CC + h * 32 + 2 * t;
#pragma unroll
            for (int nf = 0; nf < 4; nf++) {
                float2 val = make_float2(o[mf][nf][2 * rh] * inv[rr],
                                         o[mf][nf][2 * rh + 1] * inv[rr]);
                *(float2*)(op + 8 * nf) = val;
            }
        }
    }
}

// ---------------- launch ----------------
extern "C" void kernel_launch(void* const* d_in, const int* in_sizes, int n_in,
                              void* d_out, int out_size)
{
    const float* x      = (const float*)d_in[0];
    const float* relpos = (const float*)d_in[1];
    const float* Wq     = (const float*)d_in[2];
    const float* bq     = (const float*)d_in[3];
    const float* Wk     = (const float*)d_in[4];
    const float* bk     = (const float*)d_in[5];
    const float* Wv     = (const float*)d_in[6];
    const float* bv     = (const float*)d_in[7];
    const float* cw     = (const float*)d_in[8];
    const float* cb     = (const float*)d_in[9];
    const float* gamma  = (const float*)d_in[10];
    const float* beta   = (const float*)d_in[11];
    const float* mean   = (const float*)d_in[12];
    const float* var    = (const float*)d_in[13];
    const float* Wp     = (const float*)d_in[14];
    const float* bp     = (const float*)d_in[15];
    float* out = (float*)d_out;

    float *q, *k, *v, *xr, *ao;
    cudaGetSymbolAddress((void**)&q,  g_q);
    cudaGetSymbolAddress((void**)&k,  g_k);
    cudaGetSymbolAddress((void**)&v,  g_v);
    cudaGetSymbolAddress((void**)&xr, g_xr);
    cudaGetSymbolAddress((void**)&ao, g_ao);

    // 1) fused q projection (tensor mma, pipelined) + spatial-reduction conv
    int conv_blocks = (BB * NKV * CC + 255) / 256;
    qproj_conv_kernel<<<QPB2 + conv_blocks, 256>>>(x, Wq, bq, q,
                                                   cw, cb, gamma, beta, mean, var, xr);
    // 2) fused k+v projections (K d-permuted tf32; V sigma-permuted tf32)
    proj_kv_kernel<<<2 * (BB * NKV) / 64, 256>>>(xr, Wk, bk, k, Wv, bv, v, BB * NKV, NKV);
    // 3) attention: tensor-core tf32 mma, register P, prefetched float2 bias
    dim3 ag((NQ + 127) / 128, HEADS, BB);
    attn_mma_kernel<<<ag, 128>>>(q, k, v, relpos, ao);
    // 4) output projection (tensor mma, pipelined)
    oproj_kernel<<<QPB2, 256>>>(ao, Wp, bp, out);
}

// round 10
// speedup vs baseline: 1.3681x; 1.1167x over previous
#include <cuda_runtime.h>
#include <cstdint>

// ---------------- problem constants ----------------
#define BB      8
#define HEADS   4
#define NQ      3136
#define NKV     784
#define DH      32
#define CC      128
#define TN      64                 // kv tile (12 full tiles + tail of 16)
#define NFULL   12
#define VSTRIDE 26624              // 13 tiles * 2048 floats per (b,h)
#define QPB64   ((BB * NQ) / 64)   // 392
#define KVB64   ((BB * NKV) / 64)  // 98

typedef unsigned long long u64;

// ---------------- scratch (device globals; no allocation) ----------------
__device__ float g_q [BB * HEADS * NQ  * DH];      // permuted d', tf32, scaled by 32^-.5*log2e
__device__ float g_k [BB * HEADS * NKV * DH];      // permuted d', tf32
__device__ float g_v [BB * HEADS * VSTRIDE];       // sigma-permuted Vp, tf32
__device__ float g_xr[BB * NKV * CC];
__device__ float g_ao[BB * NQ  * CC];

// ---------------- helpers ----------------
__device__ __forceinline__ float to_tf32(float x) {
    float r; asm("cvt.rna.tf32.f32 %0, %1;" : "=f"(r) : "f"(x)); return r;
}
__device__ __forceinline__ float ex2(float x) {
    float r; asm("ex2.approx.f32 %0, %1;" : "=f"(r) : "f"(x)); return r;
}
__device__ __forceinline__ unsigned smem_u32(const void* p) {
    return (unsigned)__cvta_generic_to_shared(p);
}
__device__ __forceinline__ void cp16(unsigned dst, const void* src) {
    asm volatile("cp.async.cg.shared.global [%0], [%1], 16;\n" :: "r"(dst), "l"(src));
}
__device__ __forceinline__ void cp_commit() {
    asm volatile("cp.async.commit_group;\n" ::: "memory");
}
__device__ __forceinline__ void cp_wait0() {
    asm volatile("cp.async.wait_group 0;\n" ::: "memory");
}

// mma.sync m16n8k8 tf32 (base PTX, sm_80+)
__device__ __forceinline__ void mma8(float c[4], float a0, float a1, float a2, float a3,
                                     float b0, float b1) {
    asm volatile(
        "mma.sync.aligned.m16n8k8.row.col.f32.tf32.tf32.f32 "
        "{%0,%1,%2,%3}, {%4,%5,%6,%7}, {%8,%9}, {%0,%1,%2,%3};"
        : "+f"(c[0]), "+f"(c[1]), "+f"(c[2]), "+f"(c[3])
        : "r"(__float_as_uint(a0)), "r"(__float_as_uint(a1)),
          "r"(__float_as_uint(a2)), "r"(__float_as_uint(a3)),
          "r"(__float_as_uint(b0)), "r"(__float_as_uint(b1)));
}

// ---------------- tensor-core projection: Y = X(64x128 tile) @ W + b ------
// CTA = 64 rows x 128 cols, 8 warps (2m x 4n), warp tile 32x32,
// K chunks of 32, register-staged pipeline, XOR-swizzled Ws.
// MODE 0: plain fp32 row-major.   MODE 1: K (head-split, d-permute, tf32)
// MODE 2: Q (K-style + qscale).   MODE 4: V (head-split, sigma-permute, tf32)
template<int MODE>
__device__ __forceinline__ void proj_mma_body64(
    const float* __restrict__ X, const float* __restrict__ W,
    const float* __restrict__ bias, float* __restrict__ Y, int rowb)
{
    __shared__ __align__(16) float Xs[32 * 72];    // [k][m], pad 72
    __shared__ __align__(16) float Ws[32 * 136];   // [k][swz(perm(n))]

    const int tid  = threadIdx.x;
    const int lane = tid & 31, w = tid >> 5;
    const int g = lane >> 2, t = lane & 3;
    const int mw  = (w & 1) * 32;
    const int nwq = (w >> 1) * 32;
    const int w4  = (w >> 1) * 4;

    float o[2][4][4];
#pragma unroll
    for (int mf = 0; mf < 2; mf++)
#pragma unroll
        for (int j = 0; j < 4; j++)
#pragma unroll
            for (int c = 0; c < 4; c++) o[mf][j][c] = 0.f;

    float4 xa[2], wa[4];
    auto load_chunk = [&](int kc) {
#pragma unroll
        for (int i = 0; i < 2; i++) {
            int m = lane + 32 * i;
            xa[i] = *(const float4*)&X[(size_t)(rowb + m) * CC + kc + w * 4];
        }
#pragma unroll
        for (int i = 0; i < 4; i++) {
            int vv = tid + i * 256;
            int kk = vv >> 5, ng = vv & 31;
            wa[i] = *(const float4*)&W[(size_t)(kc + kk) * CC + ng * 4];
        }
    };

    load_chunk(0);
    for (int c = 0; c < 4; c++) {
        // ---- store staged chunk to smem (tf32-rounded) ----
#pragma unroll
        for (int i = 0; i < 2; i++) {
            int m = lane + 32 * i;
            float* d = &Xs[(w * 4) * 72 + m];
            d[0]   = to_tf32(xa[i].x);
            d[72]  = to_tf32(xa[i].y);
            d[144] = to_tf32(xa[i].z);
            d[216] = to_tf32(xa[i].w);
        }
#pragma unroll
        for (int i = 0; i < 4; i++) {
            int vv = tid + i * 256;
            int kk = vv >> 5, n0 = (vv & 31) * 4;
            float vals[4] = {to_tf32(wa[i].x), to_tf32(wa[i].y),
                             to_tf32(wa[i].z), to_tf32(wa[i].w)};
#pragma unroll
            for (int c2 = 0; c2 < 4; c2++) {
                int n = n0 + c2;
                int p = (n & 7) * 16 + (n >> 3);
                int sp = p ^ (((p >> 5) & 3) << 2);
                Ws[kk * 136 + sp] = vals[c2];
            }
        }
        __syncthreads();
        if (c < 3) load_chunk((c + 1) * 32);   // overlap next chunk's LDGs

#pragma unroll
        for (int s = 0; s < 4; s++) {
            const float* xr0 = &Xs[(s * 8 + t) * 72 + mw];
            const float* xr1 = xr0 + 4 * 72;
            float aA0 = xr0[g],      aA1 = xr0[g + 8];
            float aA2 = xr1[g],      aA3 = xr1[g + 8];
            float aB0 = xr0[g + 16], aB1 = xr0[g + 24];
            float aB2 = xr1[g + 16], aB3 = xr1[g + 24];

            int p0 = g * 16 + w4;
            int sp0 = p0 ^ (((p0 >> 5) & 3) << 2);
            const float* wr0 = &Ws[(s * 8 + t) * 136 + sp0];
            const float* wr1 = wr0 + 4 * 136;
            float4 b0 = *(const float4*)wr0;
            float4 b1 = *(const float4*)wr1;
            float bb0[4] = {b0.x, b0.y, b0.z, b0.w};
            float bb1[4] = {b1.x, b1.y, b1.z, b1.w};
#pragma unroll
            for (int j = 0; j < 4; j++) {
                mma8(o[0][j], aA0, aA1, aA2, aA3, bb0[j], bb1[j]);
                mma8(o[1][j], aB0, aB1, aB2, aB3, bb0[j], bb1[j]);
            }
        }
        __syncthreads();
    }

    const float qscale = 0.25503486f;   // 32^-0.5 * log2(e)
#pragma unroll
    for (int j = 0; j < 4; j++) {
        int col = nwq + 8 * j + 2 * t;
        if (MODE == 0) {
            float2 bv = *(const float2*)&bias[col];
#pragma unroll
            for (int mf = 0; mf < 2; mf++) {
                int r0 = rowb + mw + 16 * mf + g;
                *(float2*)&Y[(size_t)r0 * CC + col] =
                    make_float2(o[mf][j][0] + bv.x, o[mf][j][1] + bv.y);
                *(float2*)&Y[(size_t)(r0 + 8) * CC + col] =
                    make_float2(o[mf][j][2] + bv.x, o[mf][j][3] + bv.y);
            }
        } else {
            int h = col >> 5;
            int d0 = col & 31, d1 = d0 + 1;
            float bx = bias[col], by = bias[col + 1];
#pragma unroll
            for (int mf = 0; mf < 2; mf++) {
#pragma unroll
                for (int rh = 0; rh < 2; rh++) {
                    int row = rowb + mw + 16 * mf + g + 8 * rh;
                    float v0 = o[mf][j][2 * rh]     + bx;
                    float v1 = o[mf][j][2 * rh + 1] + by;
                    if (MODE == 2) { v0 *= qscale; v1 *= qscale; }
                    if (MODE == 4) {
                        int b = row / NKV, n = row % NKV;
                        int tile = n >> 6, rr = n & 63;
                        int off = ((rr & 7) >> 1) * 512 + 2 * (rr >> 3) + (rr & 1);
                        float* bp = &Y[(size_t)(b * HEADS + h) * VSTRIDE
                                       + tile * 2048 + off];
                        bp[d0 * 16] = to_tf32(v0);
                        bp[d1 * 16] = to_tf32(v1);
                    } else {
                        const int RPB = (MODE == 2) ? NQ : NKV;
                        int b = row / RPB, n = row % RPB;
                        int dp0 = (d0 & 3) * 8 + (d0 >> 2);
                        int dp1 = (d1 & 3) * 8 + (d1 >> 2);
                        float* bp = &Y[((size_t)(b * HEADS + h) * RPB + n) * DH];
                        bp[dp0] = to_tf32(v0);
                        bp[dp1] = to_tf32(v1);
                    }
                }
            }
        }
    }
}

// fused: q projection (tensor) + spatial-reduction conv
__global__ __launch_bounds__(256, 2) void qproj_conv_kernel(
    const float* __restrict__ x,
    const float* __restrict__ Wq, const float* __restrict__ bq, float* __restrict__ Q,
    const float* __restrict__ cw, const float* __restrict__ cb,
    const float* __restrict__ gamma, const float* __restrict__ beta,
    const float* __restrict__ mean, const float* __restrict__ var,
    float* __restrict__ xr)
{
    if (blockIdx.x < QPB64) {
        proj_mma_body64<2>(x, Wq, bq, Q, blockIdx.x * 64);
        return;
    }
    int t = (blockIdx.x - QPB64) * 256 + threadIdx.x;
    if (t >= BB * NKV * CC) return;
    int c = t & (CC - 1);
    int p = (t >> 7) % NKV;
    int b = t / (NKV * CC);
    int oy = p / 28, ox = p % 28;

    const float* xb = x + (size_t)b * NQ * CC;
    float s = 0.f;
#pragma unroll
    for (int i = 0; i < 2; i++)
#pragma unroll
        for (int j = 0; j < 2; j++)
            s += xb[(size_t)((2 * oy + i) * 56 + (2 * ox + j)) * CC + c] * cw[c * 4 + i * 2 + j];
    s += cb[c];
    float iv = gamma[c] * rsqrtf(var[c] + 1e-5f);
    xr[t] = s * iv + (beta[c] - mean[c] * iv);
}

// fused k+v projections (tensor mma)
__global__ __launch_bounds__(256, 2) void kvproj_kernel(
    const float* __restrict__ X,
    const float* __restrict__ Wk, const float* __restrict__ bk, float* __restrict__ K,
    const float* __restrict__ Wv, const float* __restrict__ bv, float* __restrict__ V)
{
    if (blockIdx.x < KVB64)
        proj_mma_body64<1>(X, Wk, bk, K, blockIdx.x * 64);
    else
        proj_mma_body64<4>(X, Wv, bv, V, (blockIdx.x - KVB64) * 64);
}

// output projection (tensor mma)
__global__ __launch_bounds__(256, 2) void oproj_kernel(
    const float* __restrict__ X, const float* __restrict__ W,
    const float* __restrict__ bias, float* __restrict__ Y)
{
    proj_mma_body64<0>(X, W, bias, Y, blockIdx.x * 64);
}

// ---------------- mma attention (register-resident P, prefetched bias) ----
#define VS_F    4608
#define SMEM_F  8736

template<int NF>
__device__ __forceinline__ void tile_body(
    const float* __restrict__ Ksm, const float* __restrict__ Vsm,
    const float (&qreg)[4][8], float (&o)[2][4][4], float (&sums)[4],
    const float* const (&rpr)[4], int ktile, int g, int t)
{
    const float L2E = 1.4426950408889634f;
    float2 bb[4];
#pragma unroll
    for (int rr = 0; rr < 4; rr++)
        bb[rr] = *(const float2*)(rpr[rr] + ktile + 2 * t);

#pragma unroll
    for (int c8 = 0; c8 < NF; c8++) {
        float2 nb[4];
        if (c8 + 1 < NF) {
#pragma unroll
            for (int rr = 0; rr < 4; rr++)
                nb[rr] = *(const float2*)(rpr[rr] + ktile + 8 * (c8 + 1) + 2 * t);
        }
        const float* kp = Ksm + (8 * c8 + g) * 36 + t * 8;
        float4 k0 = *(const float4*)kp;
        float4 k1 = *(const float4*)(kp + 4);
        float kb[8] = {k0.x, k0.y, k0.z, k0.w, k1.x, k1.y, k1.z, k1.w};
        float c0[4] = {0.f, 0.f, 0.f, 0.f};
        float c1[4] = {0.f, 0.f, 0.f, 0.f};
#pragma unroll
        for (int s = 0; s < 4; s++) {
            mma8(c0, qreg[0][2*s], qreg[1][2*s], qreg[0][2*s+1], qreg[1][2*s+1],
                 kb[2*s], kb[2*s+1]);
            mma8(c1, qreg[2][2*s], qreg[3][2*s], qreg[2][2*s+1], qreg[3][2*s+1],
                 kb[2*s], kb[2*s+1]);
        }
        float p00 = to_tf32(ex2(fmaf(bb[0].x, L2E, c0[0])));
        float p02 = to_tf32(ex2(fmaf(bb[0].y, L2E, c0[1])));
        float p10 = to_tf32(ex2(fmaf(bb[1].x, L2E, c0[2])));
        float p12 = to_tf32(ex2(fmaf(bb[1].y, L2E, c0[3])));
        float p20 = to_tf32(ex2(fmaf(bb[2].x, L2E, c1[0])));
        float p22 = to_tf32(ex2(fmaf(bb[2].y, L2E, c1[1])));
        float p30 = to_tf32(ex2(fmaf(bb[3].x, L2E, c1[2])));
        float p32 = to_tf32(ex2(fmaf(bb[3].y, L2E, c1[3])));
        sums[0] += p00 + p02; sums[1] += p10 + p12;
        sums[2] += p20 + p22; sums[3] += p30 + p32;
#pragma unroll
        for (int rr = 0; rr < 4; rr++) bb[rr] = nb[rr];
        const int posw = (c8 & 1) << 1;
        const int rh   = c8 >> 1;
#pragma unroll
        for (int nf = 0; nf < 4; nf++) {
            int d  = 8 * nf + g;
            int cc = ((d << 2) + rh) ^ ((d >> 1) & 3);
            float2 bv = *(const float2*)(Vsm + t * 516 + 4 * cc + posw);
            mma8(o[0][nf], p00, p10, p02, p12, bv.x, bv.y);
            mma8(o[1][nf], p20, p30, p22, p32, bv.x, bv.y);
        }
    }
}

__global__ __launch_bounds__(128, 3) void attn_mma_kernel(
    const float* __restrict__ q, const float* __restrict__ k, const float* __restrict__ v,
    const float* __restrict__ relpos, float* __restrict__ out)
{
    __shared__ __align__(16) float dsm[SMEM_F];

    const int b   = blockIdx.z;
    const int h   = blockIdx.y;
    const int qt  = blockIdx.x;
    const int tid = threadIdx.x;
    const int lane = tid & 31, w = tid >> 5;
    const int g = lane >> 2, t = lane & 3;
    const int q0 = qt * 128;

    const float* qb = q + (size_t)(b * HEADS + h) * NQ * DH;
    const float* kb = k + (size_t)(b * HEADS + h) * NKV * DH;
    const float* vb = v + (size_t)(b * HEADS + h) * VSTRIDE;

    float qreg[4][8];
    int qraw[4];
    const float* rpr[4];
#pragma unroll
    for (int rr = 0; rr < 4; rr++) {
        int qg = q0 + 32 * w + g + 8 * rr;
        qraw[rr] = qg;
        if (qg >= NQ) qg = NQ - 1;
        const float* qp = qb + (size_t)qg * DH + t * 8;
        float4 x0 = *(const float4*)qp;
        float4 x1 = *(const float4*)(qp + 4);
        qreg[rr][0] = x0.x; qreg[rr][1] = x0.y; qreg[rr][2] = x0.z; qreg[rr][3] = x0.w;
        qreg[rr][4] = x1.x; qreg[rr][5] = x1.y; qreg[rr][6] = x1.z; qreg[rr][7] = x1.w;
        rpr[rr] = relpos + ((size_t)h * NQ + qg) * NKV;
    }

    float o[2][4][4];
#pragma unroll
    for (int i = 0; i < 2; i++)
#pragma unroll
        for (int j = 0; j < 4; j++)
#pragma unroll
            for (int c = 0; c < 4; c++) o[i][j][c] = 0.f;
    float sums[4] = {0.f, 0.f, 0.f, 0.f};

    const unsigned kd_base = smem_u32(dsm);
    const unsigned vd_base = smem_u32(dsm + VS_F);

    {
#pragma unroll
        for (int i = 0; i < 8; i++) {
            int idx = tid + i * 128;
            if (idx < 512) {
                int r = idx >> 3, c = idx & 7;
                cp16(kd_base + r * 144 + c * 16, kb + idx * 4);
            } else {
                int j = idx - 512;
                int dst = (j >> 7) * 129 + ((j & 127) ^ ((j >> 3) & 3));
                cp16(vd_base + dst * 16, vb + j * 4);
            }
        }
    }
    cp_commit();

    for (int tt = 0; tt < 13; tt++) {
        const int buf = tt & 1;
        cp_wait0();
        __syncthreads();

        if (tt + 1 < 13) {
            const int nb = buf ^ 1;
            const unsigned kd = kd_base + nb * 9216;
            const unsigned vd = vd_base + nb * 8256;
            const float* kg = kb + (size_t)(tt + 1) * 2048;
            const float* vg = vb + (size_t)(tt + 1) * 2048;
            if (tt + 1 < NFULL) {
#pragma unroll
                for (int i = 0; i < 8; i++) {
                    int idx = tid + i * 128;
                    if (idx < 512) {
                        int r = idx >> 3, c = idx & 7;
                        cp16(kd + r * 144 + c * 16, kg + idx * 4);
                    } else {
                        int j = idx - 512;
                        int dst = (j >> 7) * 129 + ((j & 127) ^ ((j >> 3) & 3));
                        cp16(vd + dst * 16, vg + j * 4);
                    }
                }
            } else {
#pragma unroll
                for (int i = 0; i < 2; i++) {
                    int idx = tid + i * 128;
                    if (idx < 128) {
                        int r = idx >> 3, c = idx & 7;
                        cp16(kd + r * 144 + c * 16, kg + idx * 4);
                    } else {
                        int j = idx - 128;
                        int grp = j >> 5, d = j & 31;
                        int dst = grp * 129 + ((d << 2) ^ ((d >> 1) & 3));
                        cp16(vd + dst * 16, vg + grp * 512 + d * 16);
                    }
                }
            }
        }
        cp_commit();

        const float* Ksm = dsm + buf * 2304;
        const float* Vsm = dsm + VS_F + buf * 2064;
        if (tt < NFULL)
            tile_body<8>(Ksm, Vsm, qreg, o, sums, rpr, tt * TN, g, t);
        else
            tile_body<2>(Ksm, Vsm, qreg, o, sums, rpr, tt * TN, g, t);
    }

    float inv[4];
#pragma unroll
    for (int rr = 0; rr < 4; rr++) {
        float s = sums[rr];
        s += __shfl_xor_sync(0xffffffffu, s, 1);
        s += __shfl_xor_sync(0xffffffffu, s, 2);
        inv[rr] = 1.f / s;
    }
#pragma unroll
    for (int mf = 0; mf < 2; mf++) {
#pragma unroll
        for (int rh = 0; rh < 2; rh++) {
            int rr = 2 * mf + rh;
            int qg = qraw[rr];
            if (qg >= NQ) continue;
            float* op = out + ((size_t)(b * NQ + qg)) * CC + h * 32 + 2 * t;
#pragma unroll
            for (int nf = 0; nf < 4; nf++) {
                float2 val = make_float2(o[mf][nf][2 * rh] * inv[rr],
                                         o[mf][nf][2 * rh + 1] * inv[rr]);
                *(float2*)(op + 8 * nf) = val;
            }
        }
    }
}

// ---------------- launch ----------------
extern "C" void kernel_launch(void* const* d_in, const int* in_sizes, int n_in,
                              void* d_out, int out_size)
{
    const float* x      = (const float*)d_in[0];
    const float* relpos = (const float*)d_in[1];
    const float* Wq     = (const float*)d_in[2];
    const float* bq     = (const float*)d_in[3];
    const float* Wk     = (const float*)d_in[4];
    const float* bk     = (const float*)d_in[5];
    const float* Wv     = (const float*)d_in[6];
    const float* bv     = (const float*)d_in[7];
    const float* cw     = (const float*)d_in[8];
    const float* cb     = (const float*)d_in[9];
    const float* gamma  = (const float*)d_in[10];
    const float* beta   = (const float*)d_in[11];
    const float* mean   = (const float*)d_in[12];
    const float* var    = (const float*)d_in[13];
    const float* Wp     = (const float*)d_in[14];
    const float* bp     = (const float*)d_in[15];
    float* out = (float*)d_out;

    float *q, *k, *v, *xr, *ao;
    cudaGetSymbolAddress((void**)&q,  g_q);
    cudaGetSymbolAddress((void**)&k,  g_k);
    cudaGetSymbolAddress((void**)&v,  g_v);
    cudaGetSymbolAddress((void**)&xr, g_xr);
    cudaGetSymbolAddress((void**)&ao, g_ao);

    // 1) fused q projection (tensor mma, 64-row tiles) + spatial-reduction conv
    int conv_blocks = (BB * NKV * CC + 255) / 256;
    qproj_conv_kernel<<<QPB64 + conv_blocks, 256>>>(x, Wq, bq, q,
                                                    cw, cb, gamma, beta, mean, var, xr);
    // 2) fused k+v projections (tensor mma; K d-permuted, V sigma-permuted)
    kvproj_kernel<<<2 * KVB64, 256>>>(xr, Wk, bk, k, Wv, bv, v);
    // 3) attention: tensor-core tf32 mma, register P, prefetched float2 bias
    dim3 ag((NQ + 127) / 128, HEADS, BB);
    attn_mma_kernel<<<ag, 128>>>(q, k, v, relpos, ao);
    // 4) output projection (tensor mma, 64-row tiles)
    oproj_kernel<<<QPB64, 256>>>(ao, Wp, bp, out);
}